// round 11
// baseline (speedup 1.0000x reference)
#include <cuda_runtime.h>
#include <cuda_fp16.h>
#include <cstdint>

// out[b,s,o] = sum_d x[b,s,d] * w[layer_idx[s], o, d]
// B=32, S=256, D=1024, O=1024, L=32, fp32.
//
// R11: persistent grouped GEMM, warp tile enlarged 64x32 -> 64x64
// (4 warps/CTA, 128 threads, launch_bounds(128,2)). Halves per-MMA smem
// fragment traffic (96KB -> 64KB per 36KB stage), which R10's model showed
// was the co-binding resource with the tensor pipe.

constexpr int B_ = 32, S_ = 256, D_ = 1024, O_ = 1024, L_ = 32;
constexpr int KSLAB = 64, NSLABS = D_ / KSLAB;   // 16 slabs per item
constexpr int MAXT = 96;
constexpr int THREADS = 128;
constexpr int NPERS = 304;                        // 2 x 152 SMs
constexpr int ROWB = 144;                         // 128B data + 16B pad
constexpr int SA = 0, SB = 18432;                 // within a stage
constexpr int STAGE = 36864;
constexpr int NSTAGE = 3;
constexpr int SM_MBAR = 0;                        // full[st]=st*16, empty[st]=+8
constexpr int SM_TILES = 128;
constexpr int SMEM_TOTAL = SM_TILES + NSTAGE * STAGE;  // 110720 B

// ---- device scratch (no allocs allowed) ----
__device__ __half g_w16[(size_t)L_ * O_ * D_];
__device__ __half g_x16[(size_t)S_ * B_ * D_];    // [s][b][d]
__device__ int g_tile_pos[MAXT * 4];
__device__ int g_tile_layer[MAXT];
__device__ int g_ntiles;

// ---------------- helpers ----------------
__device__ __forceinline__ uint32_t smem_u32(const void* p) {
    uint32_t a;
    asm("{ .reg .u64 t; cvta.to.shared.u64 t, %1; cvt.u32.u64 %0, t; }" : "=r"(a) : "l"(p));
    return a;
}
__device__ __forceinline__ void cp16(uint32_t dst, const void* src, int srcsz) {
    asm volatile("cp.async.cg.shared.global [%0], [%1], 16, %2;"
                 :: "r"(dst), "l"(src), "r"(srcsz));
}
#define MBAR_INIT(addr, cnt) \
    asm volatile("mbarrier.init.shared.b64 [%0], %1;" :: "r"(addr), "r"(cnt) : "memory")
#define MBAR_ARRIVE(addr) \
    asm volatile("mbarrier.arrive.shared.b64 _, [%0];" :: "r"(addr) : "memory")
#define CP_MBAR_ARRIVE(addr) \
    asm volatile("cp.async.mbarrier.arrive.noinc.shared.b64 [%0];" :: "r"(addr) : "memory")
#define MBAR_WAIT(addr, par) do {                                              \
    uint32_t _m = (addr), _p = (par), _d;                                      \
    asm volatile("{ .reg .pred p; mbarrier.try_wait.parity.acquire.cta.shared::cta.b64 p, [%1], %2; selp.b32 %0,1,0,p; }" \
        : "=r"(_d) : "r"(_m), "r"(_p) : "memory");                             \
    if (!_d) {                                                                 \
        asm volatile("{ .reg .pred P; WL_%=: mbarrier.try_wait.parity.acquire.cta.shared::cta.b64 P, [%0], %1, 0x989680; @P bra.uni WD_%=; bra.uni WL_%=; WD_%=: }" \
            :: "r"(_m), "r"(_p) : "memory");                                   \
    }                                                                          \
} while (0)

__device__ __forceinline__ void ldsm4(uint32_t* r, uint32_t addr) {
    asm volatile("ldmatrix.sync.aligned.m8n8.x4.shared.b16 {%0,%1,%2,%3}, [%4];"
                 : "=r"(r[0]), "=r"(r[1]), "=r"(r[2]), "=r"(r[3]) : "r"(addr));
}
__device__ __forceinline__ void mma16816(float* c, const uint32_t* a, const uint32_t* b) {
    asm volatile(
        "mma.sync.aligned.m16n8k16.row.col.f32.f16.f16.f32 "
        "{%0,%1,%2,%3}, {%4,%5,%6,%7}, {%8,%9}, {%0,%1,%2,%3};"
        : "+f"(c[0]), "+f"(c[1]), "+f"(c[2]), "+f"(c[3])
        : "r"(a[0]), "r"(a[1]), "r"(a[2]), "r"(a[3]), "r"(b[0]), "r"(b[1]));
}

// ---------------- precompute + plan, one launch ----------------
constexpr int WBLKS = (L_ * O_ * D_) / 4 / 256;   // 32768
constexpr int XBLKS = (S_ * B_ * D_) / 4 / 256;   // 8192

__global__ void conv_kernel(const float* __restrict__ w, const float* __restrict__ x,
                            const int* __restrict__ layer_idx) {
    __shared__ int sidx[S_];
    __shared__ int tbase[L_ + 1];
    uint32_t bid = blockIdx.x;
    if (bid < WBLKS) {
        size_t i4 = ((size_t)bid * 256 + threadIdx.x) * 4;
        float4 v = *(const float4*)(w + i4);
        __half2 h0 = __floats2half2_rn(v.x, v.y);
        __half2 h1 = __floats2half2_rn(v.z, v.w);
        uint2 pk;
        pk.x = *reinterpret_cast<uint32_t*>(&h0);
        pk.y = *reinterpret_cast<uint32_t*>(&h1);
        *(uint2*)(g_w16 + i4) = pk;
    } else if (bid < WBLKS + XBLKS) {
        uint32_t e4 = (bid - WBLKS) * 256 + threadIdx.x;
        int d4 = e4 & 255;
        int b  = (e4 >> 8) & 31;
        int s  = e4 >> 13;
        float4 v = *(const float4*)(x + ((size_t)b * S_ + s) * D_ + d4 * 4);
        size_t o4 = (size_t)e4 * 4;
        __half2 h0 = __floats2half2_rn(v.x, v.y);
        __half2 h1 = __floats2half2_rn(v.z, v.w);
        uint2 ph;
        ph.x = *reinterpret_cast<uint32_t*>(&h0);
        ph.y = *reinterpret_cast<uint32_t*>(&h1);
        *(uint2*)(g_x16 + o4) = ph;
    } else {
        int t = threadIdx.x;
        sidx[t] = layer_idx[t];
        g_tile_pos[t] = -1;
        if (t < MAXT * 4 - S_) g_tile_pos[S_ + t] = -1;
        __syncthreads();
        int my_l = sidx[t];
        int rank = 0;
        for (int j = 0; j < t; j++) rank += (sidx[j] == my_l) ? 1 : 0;
        if (t == 0) {
            int cnt[L_];
            for (int l = 0; l < L_; l++) cnt[l] = 0;
            for (int j = 0; j < S_; j++) cnt[sidx[j]]++;
            int acc = 0;
            for (int l = 0; l < L_; l++) { tbase[l] = acc; acc += (cnt[l] + 3) >> 2; }
            g_ntiles = acc;
        }
        __syncthreads();
        int tile = tbase[my_l] + (rank >> 2);
        g_tile_pos[tile * 4 + (rank & 3)] = t;
        if ((rank & 3) == 0) g_tile_layer[tile] = my_l;
    }
}

// ---------------- persistent grouped GEMM, 4 warps of 64x64 --------------
extern __shared__ char smem[];

__global__ __launch_bounds__(THREADS, 2)
void moshi_gemm_kernel(float* __restrict__ out) {
    const int tid = threadIdx.x;
    const int lane = tid & 31;
    const int wid = tid >> 5;
    const int warp_m = wid & 1;        // 2 warps in M
    const int warp_n = wid >> 1;       // 2 warps in N
    const int m64 = warp_m * 64;
    const int n64 = warp_n * 64;
    const uint32_t sbase = smem_u32(smem);

    const int n_items = g_ntiles * 8;  // (tile, nb) pairs
    int my_n = 0;
    for (int it = blockIdx.x; it < n_items; it += NPERS) my_n++;
    if (my_n == 0) return;
    const int total_slabs = my_n * NSLABS;

    if (tid == 0) {
#pragma unroll
        for (int st = 0; st < NSTAGE; st++) {
            MBAR_INIT(sbase + SM_MBAR + st * 16, THREADS);
            MBAR_INIT(sbase + SM_MBAR + st * 16 + 8, THREADS);
        }
    }
    __syncthreads();

    // ---- producer mapping: thread t loads full row t (8 chunks A + 8 B) ----
    const int ar = tid;                 // 0..127
    const int aslot = ar >> 5;
    const uint32_t dRow = (uint32_t)ar * ROWB;
    const uint32_t aOff = (uint32_t)(m64 + (lane & 15)) * ROWB + (lane >> 4) * 16;
    const uint32_t bOff = (uint32_t)(n64 + (lane & 7) + ((lane >> 4) << 3)) * ROWB
                          + ((lane >> 3) & 1) * 16;

    // ---- producer item state ----
    int p_li = -1;
    const __half* ax = g_x16;
    const __half* bw = g_w16;
    int asz = 0;

    auto setp = [&](int li) {
        const int item = blockIdx.x + li * NPERS;
        const int tile = item >> 3;
        const int nb = item & 7;
        const int l = g_tile_layer[tile];
        const int aspos = g_tile_pos[tile * 4 + aslot];
        asz = (aspos >= 0) ? 16 : 0;
        ax = g_x16 + ((aspos >= 0)
                ? ((size_t)aspos * B_ + (ar & 31)) * D_ : 0);
        bw = g_w16 + ((size_t)l * O_ + nb * 128 + ar) * D_;
    };

    auto produce = [&](int sg) {
        const int li = sg >> 4;
        if (li != p_li) { setp(li); p_li = li; }
        const int st = sg % NSTAGE;
        const uint32_t s0 = sbase + SM_TILES + st * STAGE;
        const int k0 = (sg & 15) * KSLAB;
#pragma unroll
        for (int c = 0; c < 8; c++)
            cp16(s0 + SA + dRow + c * 16, ax + k0 + c * 8, asz);
#pragma unroll
        for (int c = 0; c < 8; c++)
            cp16(s0 + SB + dRow + c * 16, bw + k0 + c * 8, 16);
        CP_MBAR_ARRIVE(sbase + SM_MBAR + st * 16);
    };

    float acc[4][8][4];
#pragma unroll
    for (int i = 0; i < 4; i++)
#pragma unroll
        for (int j = 0; j < 8; j++)
#pragma unroll
            for (int q = 0; q < 4; q++) acc[i][j][q] = 0.0f;

    produce(0);
    produce(1);

    for (int sg = 0; sg < total_slabs; sg++) {
        const int ps = sg + 2;
        if (ps < total_slabs) {
            const int pw = ps / NSTAGE;
            if (pw >= 1) MBAR_WAIT(sbase + SM_MBAR + (ps % NSTAGE) * 16 + 8, (pw - 1) & 1);
            produce(ps);
        }
        const int st = sg % NSTAGE;
        MBAR_WAIT(sbase + SM_MBAR + st * 16, (sg / NSTAGE) & 1);
        const uint32_t sstage = sbase + SM_TILES + st * STAGE;
#pragma unroll
        for (int kk = 0; kk < 4; kk++) {
            uint32_t ah[4][4];
#pragma unroll
            for (int mi = 0; mi < 4; mi++)
                ldsm4(ah[mi], sstage + SA + aOff + mi * (16 * ROWB) + kk * 32);
            uint32_t bb[8][2];
#pragma unroll
            for (int p = 0; p < 4; p++) {
                uint32_t r[4];
                ldsm4(r, sstage + SB + bOff + p * (16 * ROWB) + kk * 32);
                bb[2 * p][0] = r[0]; bb[2 * p][1] = r[1];
                bb[2 * p + 1][0] = r[2]; bb[2 * p + 1][1] = r[3];
            }
#pragma unroll
            for (int mi = 0; mi < 4; mi++)
#pragma unroll
                for (int ni = 0; ni < 8; ni++)
                    mma16816(acc[mi][ni], ah[mi], bb[ni]);
        }
        MBAR_ARRIVE(sbase + SM_MBAR + st * 16 + 8);

        // ---- item boundary: epilogue + acc reset ----
        if ((sg & 15) == 15) {
            const int item = blockIdx.x + (sg >> 4) * NPERS;
            const int tile = item >> 3;
            const int otile = (item & 7) * 128;
            const int gcol = otile + n64 + 2 * (lane & 3);
#pragma unroll
            for (int mi = 0; mi < 4; mi++) {
                const int row0 = m64 + mi * 16 + (lane >> 2);
                const int slot = row0 >> 5;
                const int spos = g_tile_pos[tile * 4 + slot];
                if (spos >= 0) {
                    float* base0 = out + ((size_t)(row0 & 31) * S_ + spos) * O_ + gcol;
                    float* base1 = out + ((size_t)((row0 + 8) & 31) * S_ + spos) * O_ + gcol;
#pragma unroll
                    for (int ni = 0; ni < 8; ni++) {
                        *(float2*)(base0 + ni * 8) =
                            make_float2(acc[mi][ni][0], acc[mi][ni][1]);
                        *(float2*)(base1 + ni * 8) =
                            make_float2(acc[mi][ni][2], acc[mi][ni][3]);
                    }
                }
#pragma unroll
                for (int ni = 0; ni < 8; ni++)
#pragma unroll
                    for (int q = 0; q < 4; q++) acc[mi][ni][q] = 0.0f;
            }
        }
    }
}

extern "C" void kernel_launch(void* const* d_in, const int* in_sizes, int n_in,
                              void* d_out, int out_size) {
    const float* x = (const float*)d_in[0];
    const int* idx = (const int*)d_in[1];
    const float* w = (const float*)d_in[2];
    float* out = (float*)d_out;

    conv_kernel<<<WBLKS + XBLKS + 1, 256>>>(w, x, idx);

    static bool attr_set = false;
    if (!attr_set) {
        cudaFuncSetAttribute(moshi_gemm_kernel,
                             cudaFuncAttributeMaxDynamicSharedMemorySize, SMEM_TOTAL);
        attr_set = true;
    }
    moshi_gemm_kernel<<<NPERS, THREADS, SMEM_TOTAL>>>(out);
}

// round 12
// speedup vs baseline: 1.3683x; 1.3683x over previous
#include <cuda_runtime.h>
#include <cuda_fp16.h>
#include <cuda.h>
#include <cstdint>

// out[b,s,o] = sum_d x[b,s,d] * w[layer_idx[s], o, d]
// B=32, S=256, D=1024, O=1024, L=32, fp32.
//
// R12: R10's persistent grouped GEMM but the producer's 23M 16B cp.async ops
// (shown to be the issue-rate binder: ~1 LDGSTS/cyc/SM ~= 80us ~= measured)
// are replaced by TMA: 5 cp.async.bulk.tensor.2d loads per K-slab issued by
// one elected thread, mbarrier complete_tx. SW128-swizzled smem, ldsm
// addresses XOR-adjusted. TMA descriptors via cuTensorMapEncodeTiled
// (driver entry point through cudart), passed __grid_constant__.

constexpr int B_ = 32, S_ = 256, D_ = 1024, O_ = 1024, L_ = 32;
constexpr int KSLAB = 64, NSLABS = D_ / KSLAB;   // 16 slabs per item
constexpr int MAXT = 96;
constexpr int THREADS = 256;
constexpr int NPERS = 304;                        // 2 x 152 SMs
constexpr int SA = 0, SB = 16384;                 // within a stage (128B rows)
constexpr int STAGE = 32768;
constexpr int NSTAGE = 3;
constexpr int SM_MBAR = 0;                        // full[st]=st*16, empty[st]=+8
constexpr int SM_TILES = 1024;                    // 1024-aligned for SW128
constexpr int SMEM_TOTAL = SM_TILES + NSTAGE * STAGE;  // 99328 B
constexpr uint32_t TX_BYTES = 32768;              // per-slab TMA bytes

// ---- device scratch (no allocs allowed) ----
__device__ __align__(1024) __half g_w16[(size_t)L_ * O_ * D_];
__device__ __align__(1024) __half g_x16[(size_t)S_ * B_ * D_];   // [s][b][d]
__device__ int g_tile_pos[MAXT * 4];
__device__ int g_tile_layer[MAXT];
__device__ int g_ntiles;

// ---------------- helpers ----------------
__device__ __forceinline__ uint32_t smem_u32(const void* p) {
    uint32_t a;
    asm("{ .reg .u64 t; cvta.to.shared.u64 t, %1; cvt.u32.u64 %0, t; }" : "=r"(a) : "l"(p));
    return a;
}
#define MBAR_INIT(addr, cnt) \
    asm volatile("mbarrier.init.shared.b64 [%0], %1;" :: "r"(addr), "r"(cnt) : "memory")
#define MBAR_ARRIVE(addr) \
    asm volatile("mbarrier.arrive.shared.b64 _, [%0];" :: "r"(addr) : "memory")
#define MBAR_EXPECT_TX(addr, tx) \
    asm volatile("mbarrier.arrive.expect_tx.shared.b64 _, [%0], %1;" \
                 :: "r"(addr), "r"(tx) : "memory")
#define MBAR_WAIT(addr, par) do {                                              \
    uint32_t _m = (addr), _p = (par), _d;                                      \
    asm volatile("{ .reg .pred p; mbarrier.try_wait.parity.acquire.cta.shared::cta.b64 p, [%1], %2; selp.b32 %0,1,0,p; }" \
        : "=r"(_d) : "r"(_m), "r"(_p) : "memory");                             \
    if (!_d) {                                                                 \
        asm volatile("{ .reg .pred P; WL_%=: mbarrier.try_wait.parity.acquire.cta.shared::cta.b64 P, [%0], %1, 0x989680; @P bra.uni WD_%=; bra.uni WL_%=; WD_%=: }" \
            :: "r"(_m), "r"(_p) : "memory");                                   \
    }                                                                          \
} while (0)

__device__ __forceinline__ void tma2d(uint32_t dst, const CUtensorMap* m,
                                      int cx, int cy, uint32_t mbar) {
    asm volatile(
        "cp.async.bulk.tensor.2d.shared::cta.global.tile.mbarrier::complete_tx::bytes "
        "[%0], [%1, {%2, %3}], [%4];"
        :: "r"(dst), "l"(m), "r"(cx), "r"(cy), "r"(mbar) : "memory");
}
__device__ __forceinline__ void ldsm4(uint32_t* r, uint32_t addr) {
    asm volatile("ldmatrix.sync.aligned.m8n8.x4.shared.b16 {%0,%1,%2,%3}, [%4];"
                 : "=r"(r[0]), "=r"(r[1]), "=r"(r[2]), "=r"(r[3]) : "r"(addr));
}
__device__ __forceinline__ void mma16816(float* c, const uint32_t* a, const uint32_t* b) {
    asm volatile(
        "mma.sync.aligned.m16n8k16.row.col.f32.f16.f16.f32 "
        "{%0,%1,%2,%3}, {%4,%5,%6,%7}, {%8,%9}, {%0,%1,%2,%3};"
        : "+f"(c[0]), "+f"(c[1]), "+f"(c[2]), "+f"(c[3])
        : "r"(a[0]), "r"(a[1]), "r"(a[2]), "r"(a[3]), "r"(b[0]), "r"(b[1]));
}

// ---------------- precompute + plan, one launch ----------------
constexpr int WBLKS = (L_ * O_ * D_) / 4 / 256;   // 32768
constexpr int XBLKS = (S_ * B_ * D_) / 4 / 256;   // 8192

__global__ void conv_kernel(const float* __restrict__ w, const float* __restrict__ x,
                            const int* __restrict__ layer_idx) {
    __shared__ int sidx[S_];
    __shared__ int tbase[L_ + 1];
    uint32_t bid = blockIdx.x;
    if (bid < WBLKS) {
        size_t i4 = ((size_t)bid * 256 + threadIdx.x) * 4;
        float4 v = *(const float4*)(w + i4);
        __half2 h0 = __floats2half2_rn(v.x, v.y);
        __half2 h1 = __floats2half2_rn(v.z, v.w);
        uint2 pk;
        pk.x = *reinterpret_cast<uint32_t*>(&h0);
        pk.y = *reinterpret_cast<uint32_t*>(&h1);
        *(uint2*)(g_w16 + i4) = pk;
    } else if (bid < WBLKS + XBLKS) {
        uint32_t e4 = (bid - WBLKS) * 256 + threadIdx.x;
        int d4 = e4 & 255;
        int b  = (e4 >> 8) & 31;
        int s  = e4 >> 13;
        float4 v = *(const float4*)(x + ((size_t)b * S_ + s) * D_ + d4 * 4);
        size_t o4 = (size_t)e4 * 4;
        __half2 h0 = __floats2half2_rn(v.x, v.y);
        __half2 h1 = __floats2half2_rn(v.z, v.w);
        uint2 ph;
        ph.x = *reinterpret_cast<uint32_t*>(&h0);
        ph.y = *reinterpret_cast<uint32_t*>(&h1);
        *(uint2*)(g_x16 + o4) = ph;
    } else {
        int t = threadIdx.x;
        sidx[t] = layer_idx[t];
        g_tile_pos[t] = -1;
        if (t < MAXT * 4 - S_) g_tile_pos[S_ + t] = -1;
        __syncthreads();
        int my_l = sidx[t];
        int rank = 0;
        for (int j = 0; j < t; j++) rank += (sidx[j] == my_l) ? 1 : 0;
        if (t == 0) {
            int cnt[L_];
            for (int l = 0; l < L_; l++) cnt[l] = 0;
            for (int j = 0; j < S_; j++) cnt[sidx[j]]++;
            int acc = 0;
            for (int l = 0; l < L_; l++) { tbase[l] = acc; acc += (cnt[l] + 3) >> 2; }
            g_ntiles = acc;
        }
        __syncthreads();
        int tile = tbase[my_l] + (rank >> 2);
        g_tile_pos[tile * 4 + (rank & 3)] = t;
        if ((rank & 3) == 0) g_tile_layer[tile] = my_l;
    }
}

// ---------------- persistent grouped GEMM, TMA producer ----------------
extern __shared__ char smem[];

__global__ __launch_bounds__(THREADS, 2)
void moshi_gemm_kernel(const __grid_constant__ CUtensorMap tmaA,
                       const __grid_constant__ CUtensorMap tmaB,
                       float* __restrict__ out) {
    const int tid = threadIdx.x;
    const int lane = tid & 31;
    const int wid = tid >> 5;
    const int warp_m = wid & 1;        // 2 warps in M
    const int warp_n = wid >> 1;       // 4 warps in N
    const int m64 = warp_m * 64;
    const int n32 = warp_n * 32;
    const uint32_t sbase = smem_u32(smem);

    const int n_items = g_ntiles * 8;  // (tile, nb) pairs
    int my_n = 0;
    for (int it = blockIdx.x; it < n_items; it += NPERS) my_n++;
    if (my_n == 0) return;
    const int total_slabs = my_n * NSLABS;

    if (tid == 0) {
#pragma unroll
        for (int st = 0; st < NSTAGE; st++) {
            MBAR_INIT(sbase + SM_MBAR + st * 16, 1);        // full: 1 expect_tx arrive
            MBAR_INIT(sbase + SM_MBAR + st * 16 + 8, THREADS);  // empty
        }
    }
    __syncthreads();

    // ---- consumer ldsm addressing (SW128 swizzle) ----
    const uint32_t swz = (uint32_t)(lane & 7) * 16;
    const uint32_t aRowOff = (uint32_t)(m64 + (lane & 15)) * 128;
    const uint32_t bRowOff = (uint32_t)(n32 + (lane & 7) + ((lane >> 4) << 3)) * 128;
    const uint32_t hiA = (uint32_t)(lane >> 4) * 16;
    const uint32_t hiB = (uint32_t)((lane >> 3) & 1) * 16;
    uint32_t aCh[4], bCh[4];
#pragma unroll
    for (int kk = 0; kk < 4; kk++) {
        aCh[kk] = ((uint32_t)kk * 32 + hiA) ^ swz;
        bCh[kk] = ((uint32_t)kk * 32 + hiB) ^ swz;
    }

    // ---- producer (tid 0): TMA loads per slab ----
    auto produce = [&](int sg) {
        const int item = blockIdx.x + (sg >> 4) * NPERS;
        const int tile = item >> 3;
        const int nb = item & 7;
        const int l = g_tile_layer[tile];
        const int st = sg % NSTAGE;
        const uint32_t s0 = sbase + SM_TILES + st * STAGE;
        const uint32_t mbar = sbase + SM_MBAR + st * 16;
        const int kx = (sg & 15) * KSLAB;      // element coord in D
        MBAR_EXPECT_TX(mbar, TX_BYTES);
        tma2d(s0 + SB, &tmaB, kx, l * O_ + nb * 128, mbar);
        const int p0 = g_tile_pos[tile * 4];
#pragma unroll
        for (int q = 0; q < 4; q++) {
            int sp = g_tile_pos[tile * 4 + q];
            if (sp < 0) sp = p0;               // duplicate rows; epilogue skips
            tma2d(s0 + SA + q * 4096, &tmaA, kx, sp * B_, mbar);
        }
    };

    float acc[4][4][4];
#pragma unroll
    for (int i = 0; i < 4; i++)
#pragma unroll
        for (int j = 0; j < 4; j++)
#pragma unroll
            for (int q = 0; q < 4; q++) acc[i][j][q] = 0.0f;

    if (tid == 0) { produce(0); produce(1); }

    for (int sg = 0; sg < total_slabs; sg++) {
        const int ps = sg + 2;
        if (tid == 0 && ps < total_slabs) {
            const int pw = ps / NSTAGE;
            if (pw >= 1) MBAR_WAIT(sbase + SM_MBAR + (ps % NSTAGE) * 16 + 8, (pw - 1) & 1);
            produce(ps);
        }
        const int st = sg % NSTAGE;
        MBAR_WAIT(sbase + SM_MBAR + st * 16, (sg / NSTAGE) & 1);
        const uint32_t aT = sbase + SM_TILES + st * STAGE + SA + aRowOff;
        const uint32_t bT = sbase + SM_TILES + st * STAGE + SB + bRowOff;
#pragma unroll
        for (int kk = 0; kk < 4; kk++) {
            uint32_t ah[4][4];
#pragma unroll
            for (int mi = 0; mi < 4; mi++)
                ldsm4(ah[mi], aT + mi * 2048 + aCh[kk]);
            uint32_t bb[4][2];
#pragma unroll
            for (int p = 0; p < 2; p++) {
                uint32_t r[4];
                ldsm4(r, bT + p * 2048 + bCh[kk]);
                bb[2 * p][0] = r[0]; bb[2 * p][1] = r[1];
                bb[2 * p + 1][0] = r[2]; bb[2 * p + 1][1] = r[3];
            }
#pragma unroll
            for (int mi = 0; mi < 4; mi++)
#pragma unroll
                for (int ni = 0; ni < 4; ni++)
                    mma16816(acc[mi][ni], ah[mi], bb[ni]);
        }
        MBAR_ARRIVE(sbase + SM_MBAR + st * 16 + 8);

        // ---- item boundary: epilogue + acc reset ----
        if ((sg & 15) == 15) {
            const int item = blockIdx.x + (sg >> 4) * NPERS;
            const int tile = item >> 3;
            const int otile = (item & 7) * 128;
            const int gcol = otile + n32 + 2 * (lane & 3);
#pragma unroll
            for (int mi = 0; mi < 4; mi++) {
                const int row0 = m64 + mi * 16 + (lane >> 2);
                const int slot = row0 >> 5;
                const int spos = g_tile_pos[tile * 4 + slot];
                if (spos >= 0) {
                    float* base0 = out + ((size_t)(row0 & 31) * S_ + spos) * O_ + gcol;
                    float* base1 = out + ((size_t)((row0 + 8) & 31) * S_ + spos) * O_ + gcol;
#pragma unroll
                    for (int ni = 0; ni < 4; ni++) {
                        *(float2*)(base0 + ni * 8) =
                            make_float2(acc[mi][ni][0], acc[mi][ni][1]);
                        *(float2*)(base1 + ni * 8) =
                            make_float2(acc[mi][ni][2], acc[mi][ni][3]);
                    }
                }
#pragma unroll
                for (int ni = 0; ni < 4; ni++)
#pragma unroll
                    for (int q = 0; q < 4; q++) acc[mi][ni][q] = 0.0f;
            }
        }
    }
}

// ---------------- host ----------------
typedef CUresult (*tma_encode_fn)(
    CUtensorMap*, CUtensorMapDataType, cuuint32_t, void*,
    const cuuint64_t*, const cuuint64_t*, const cuuint32_t*, const cuuint32_t*,
    CUtensorMapInterleave, CUtensorMapSwizzle, CUtensorMapL2promotion,
    CUtensorMapFloatOOBfill);

extern "C" void kernel_launch(void* const* d_in, const int* in_sizes, int n_in,
                              void* d_out, int out_size) {
    const float* x = (const float*)d_in[0];
    const int* idx = (const int*)d_in[1];
    const float* w = (const float*)d_in[2];
    float* out = (float*)d_out;

    static CUtensorMap h_tma_a, h_tma_b;
    static bool init_done = false;
    if (!init_done) {
        cudaFuncSetAttribute(moshi_gemm_kernel,
                             cudaFuncAttributeMaxDynamicSharedMemorySize, SMEM_TOTAL);
        void* pa = nullptr; void* pb = nullptr;
        cudaGetSymbolAddress(&pa, g_x16);
        cudaGetSymbolAddress(&pb, g_w16);
        tma_encode_fn enc = nullptr;
        cudaDriverEntryPointQueryResult qr;
        cudaGetDriverEntryPointByVersion("cuTensorMapEncodeTiled", (void**)&enc,
                                         12000, cudaEnableDefault, &qr);
        cuuint64_t dimsA[2] = {(cuuint64_t)D_, (cuuint64_t)(S_ * B_)};
        cuuint64_t strA[1]  = {(cuuint64_t)D_ * 2};
        cuuint32_t boxA[2]  = {64, 32};
        cuuint32_t es[2]    = {1, 1};
        enc(&h_tma_a, CU_TENSOR_MAP_DATA_TYPE_FLOAT16, 2, pa, dimsA, strA, boxA, es,
            CU_TENSOR_MAP_INTERLEAVE_NONE, CU_TENSOR_MAP_SWIZZLE_128B,
            CU_TENSOR_MAP_L2_PROMOTION_L2_128B, CU_TENSOR_MAP_FLOAT_OOB_FILL_NONE);
        cuuint64_t dimsB[2] = {(cuuint64_t)D_, (cuuint64_t)(L_ * O_)};
        cuuint64_t strB[1]  = {(cuuint64_t)D_ * 2};
        cuuint32_t boxB[2]  = {64, 128};
        enc(&h_tma_b, CU_TENSOR_MAP_DATA_TYPE_FLOAT16, 2, pb, dimsB, strB, boxB, es,
            CU_TENSOR_MAP_INTERLEAVE_NONE, CU_TENSOR_MAP_SWIZZLE_128B,
            CU_TENSOR_MAP_L2_PROMOTION_L2_128B, CU_TENSOR_MAP_FLOAT_OOB_FILL_NONE);
        init_done = true;
    }

    conv_kernel<<<WBLKS + XBLKS + 1, 256>>>(w, x, idx);
    moshi_gemm_kernel<<<NPERS, THREADS, SMEM_TOTAL>>>(h_tma_a, h_tma_b, out);
}

// round 13
// speedup vs baseline: 1.5293x; 1.1177x over previous
#include <cuda_runtime.h>
#include <cuda_fp16.h>
#include <cuda.h>
#include <cstdint>

// out[b,s,o] = sum_d x[b,s,d] * w[layer_idx[s], o, d]
// B=32, S=256, D=1024, O=1024, L=32, fp32.
//
// R13: W conversion pass eliminated. B tiles TMA'd as *fp32* straight from
// the input weight tensor (SW128, KSLAB=32); consumer builds fp16 B frags
// with ld.shared.v2.f32 + cvt.rn.f16x2.f32. A stays fp16 (X conv kept,
// small). Dual rings: B every slab, A every other slab (KSLAB_A=64),
// separate mbarrier pairs. Persistent CTAs as R12.

constexpr int B_ = 32, S_ = 256, D_ = 1024, O_ = 1024, L_ = 32;
constexpr int MAXT = 96;
constexpr int THREADS = 256;
constexpr int NPERS = 304;
constexpr int NST = 3;
constexpr int TSZ = 16384;                        // bytes per stage (A and B)
constexpr int SM_MBAR = 0;   // BFull st*16, BEmpty +8; AFull 64+st*16, AEmpty +8
constexpr int SM_TILES = 1024;
constexpr int A_OFF = 0, B_OFF = NST * TSZ;       // within tiles region
constexpr int SMEM_TOTAL = SM_TILES + 2 * NST * TSZ;   // 99328

// ---- device scratch ----
__device__ __align__(1024) __half g_x16[(size_t)S_ * B_ * D_];   // [s][b][d]
__device__ int g_tile_pos[MAXT * 4];
__device__ int g_tile_layer[MAXT];
__device__ int g_ntiles;

// ---------------- helpers ----------------
__device__ __forceinline__ uint32_t smem_u32(const void* p) {
    uint32_t a;
    asm("{ .reg .u64 t; cvta.to.shared.u64 t, %1; cvt.u32.u64 %0, t; }" : "=r"(a) : "l"(p));
    return a;
}
#define MBAR_INIT(addr, cnt) \
    asm volatile("mbarrier.init.shared.b64 [%0], %1;" :: "r"(addr), "r"(cnt) : "memory")
#define MBAR_ARRIVE(addr) \
    asm volatile("mbarrier.arrive.shared.b64 _, [%0];" :: "r"(addr) : "memory")
#define MBAR_EXPECT_TX(addr, tx) \
    asm volatile("mbarrier.arrive.expect_tx.shared.b64 _, [%0], %1;" \
                 :: "r"(addr), "r"(tx) : "memory")
#define MBAR_WAIT(addr, par) do {                                              \
    uint32_t _m = (addr), _p = (par), _d;                                      \
    asm volatile("{ .reg .pred p; mbarrier.try_wait.parity.acquire.cta.shared::cta.b64 p, [%1], %2; selp.b32 %0,1,0,p; }" \
        : "=r"(_d) : "r"(_m), "r"(_p) : "memory");                             \
    if (!_d) {                                                                 \
        asm volatile("{ .reg .pred P; WL_%=: mbarrier.try_wait.parity.acquire.cta.shared::cta.b64 P, [%0], %1, 0x989680; @P bra.uni WD_%=; bra.uni WL_%=; WD_%=: }" \
            :: "r"(_m), "r"(_p) : "memory");                                   \
    }                                                                          \
} while (0)

__device__ __forceinline__ void tma2d(uint32_t dst, const CUtensorMap* m,
                                      int cx, int cy, uint32_t mbar) {
    asm volatile(
        "cp.async.bulk.tensor.2d.shared::cta.global.tile.mbarrier::complete_tx::bytes "
        "[%0], [%1, {%2, %3}], [%4];"
        :: "r"(dst), "l"(m), "r"(cx), "r"(cy), "r"(mbar) : "memory");
}
__device__ __forceinline__ void ldsm4(uint32_t* r, uint32_t addr) {
    asm volatile("ldmatrix.sync.aligned.m8n8.x4.shared.b16 {%0,%1,%2,%3}, [%4];"
                 : "=r"(r[0]), "=r"(r[1]), "=r"(r[2]), "=r"(r[3]) : "r"(addr));
}
__device__ __forceinline__ void lds2f(float& a, float& b, uint32_t addr) {
    asm volatile("ld.shared.v2.f32 {%0,%1}, [%2];" : "=f"(a), "=f"(b) : "r"(addr));
}
__device__ __forceinline__ uint32_t pkf16(float lo, float hi) {
    uint32_t d;
    asm("cvt.rn.f16x2.f32 %0, %1, %2;" : "=r"(d) : "f"(hi), "f"(lo));
    return d;
}
__device__ __forceinline__ void mma16816(float* c, const uint32_t* a, const uint32_t* b) {
    asm volatile(
        "mma.sync.aligned.m16n8k16.row.col.f32.f16.f16.f32 "
        "{%0,%1,%2,%3}, {%4,%5,%6,%7}, {%8,%9}, {%0,%1,%2,%3};"
        : "+f"(c[0]), "+f"(c[1]), "+f"(c[2]), "+f"(c[3])
        : "r"(a[0]), "r"(a[1]), "r"(a[2]), "r"(a[3]), "r"(b[0]), "r"(b[1]));
}

// ---------------- precompute X + plan, one launch ----------------
constexpr int XBLKS = (S_ * B_ * D_) / 4 / 256;   // 8192

__global__ void conv_kernel(const float* __restrict__ x,
                            const int* __restrict__ layer_idx) {
    __shared__ int sidx[S_];
    __shared__ int tbase[L_ + 1];
    uint32_t bid = blockIdx.x;
    if (bid < XBLKS) {
        uint32_t e4 = bid * 256 + threadIdx.x;
        int d4 = e4 & 255;
        int b  = (e4 >> 8) & 31;
        int s  = e4 >> 13;
        float4 v = *(const float4*)(x + ((size_t)b * S_ + s) * D_ + d4 * 4);
        size_t o4 = (size_t)e4 * 4;
        __half2 h0 = __floats2half2_rn(v.x, v.y);
        __half2 h1 = __floats2half2_rn(v.z, v.w);
        uint2 ph;
        ph.x = *reinterpret_cast<uint32_t*>(&h0);
        ph.y = *reinterpret_cast<uint32_t*>(&h1);
        *(uint2*)(g_x16 + o4) = ph;
    } else {
        int t = threadIdx.x;
        sidx[t] = layer_idx[t];
        g_tile_pos[t] = -1;
        if (t < MAXT * 4 - S_) g_tile_pos[S_ + t] = -1;
        __syncthreads();
        int my_l = sidx[t];
        int rank = 0;
        for (int j = 0; j < t; j++) rank += (sidx[j] == my_l) ? 1 : 0;
        if (t == 0) {
            int cnt[L_];
            for (int l = 0; l < L_; l++) cnt[l] = 0;
            for (int j = 0; j < S_; j++) cnt[sidx[j]]++;
            int acc = 0;
            for (int l = 0; l < L_; l++) { tbase[l] = acc; acc += (cnt[l] + 3) >> 2; }
            g_ntiles = acc;
        }
        __syncthreads();
        int tile = tbase[my_l] + (rank >> 2);
        g_tile_pos[tile * 4 + (rank & 3)] = t;
        if ((rank & 3) == 0) g_tile_layer[tile] = my_l;
    }
}

// ---------------- persistent grouped GEMM ----------------
extern __shared__ char smem[];

__global__ __launch_bounds__(THREADS, 2)
void moshi_gemm_kernel(const __grid_constant__ CUtensorMap tmaA,
                       const __grid_constant__ CUtensorMap tmaB,
                       float* __restrict__ out) {
    const int tid = threadIdx.x;
    const int lane = tid & 31;
    const int wid = tid >> 5;
    const int warp_m = wid & 1;        // 2 warps in M
    const int warp_n = wid >> 1;       // 4 warps in N
    const int m64 = warp_m * 64;
    const int n32 = warp_n * 32;
    const uint32_t sbase = smem_u32(smem);

    const int n_items = g_ntiles * 8;
    int my_n = 0;
    for (int it = blockIdx.x; it < n_items; it += NPERS) my_n++;
    if (my_n == 0) return;
    const int totB = my_n * 32;        // B slabs (KSLAB=32)
    const int totA = my_n * 16;        // A slabs (KSLAB=64)

    if (tid == 0) {
#pragma unroll
        for (int st = 0; st < NST; st++) {
            MBAR_INIT(sbase + st * 16, 1);            // B full
            MBAR_INIT(sbase + st * 16 + 8, THREADS);  // B empty
            MBAR_INIT(sbase + 64 + st * 16, 1);       // A full
            MBAR_INIT(sbase + 64 + st * 16 + 8, THREADS);
        }
    }
    __syncthreads();

    // ---- A consumer addressing (fp16, SW128, 128B rows) ----
    const uint32_t swz = (uint32_t)(lane & 7) * 16;
    const uint32_t aRowOff = (uint32_t)(m64 + (lane & 15)) * 128;
    const uint32_t hiA = (uint32_t)(lane >> 4) * 16;
    uint32_t aCh[4];
#pragma unroll
    for (int k4 = 0; k4 < 4; k4++) aCh[k4] = ((uint32_t)k4 * 32 + hiA) ^ swz;

    // ---- B consumer addressing (fp32, SW128, 128B rows of 32 f32) ----
    const uint32_t bRow = (uint32_t)(n32 + (lane >> 2)) * 128;
    const uint32_t klow = (uint32_t)(lane & 3) * 8;
    const uint32_t xr = (((uint32_t)(lane >> 2) & 7)) << 4;
    uint32_t bO0[2], bO1[2];
#pragma unroll
    for (int kk = 0; kk < 2; kk++) {
        bO0[kk] = ((uint32_t)kk * 64 + klow) ^ xr;
        bO1[kk] = ((uint32_t)kk * 64 + klow + 32) ^ xr;
    }

    // ---- producers (tid 0) ----
    auto produceB = [&](int sg) {
        const int st = sg % NST;
        const int item = blockIdx.x + (sg >> 5) * NPERS;
        const int tile = item >> 3;
        const int nb = item & 7;
        const int l = g_tile_layer[tile];
        const uint32_t mbar = sbase + st * 16;
        MBAR_EXPECT_TX(mbar, (uint32_t)TSZ);
        tma2d(sbase + SM_TILES + B_OFF + st * TSZ, &tmaB,
              (sg & 31) * 32, l * O_ + nb * 128, mbar);
    };
    auto produceA = [&](int ag) {
        const int st = ag % NST;
        const int item = blockIdx.x + (ag >> 4) * NPERS;
        const int tile = item >> 3;
        const uint32_t mbar = sbase + 64 + st * 16;
        const uint32_t s0 = sbase + SM_TILES + A_OFF + st * TSZ;
        MBAR_EXPECT_TX(mbar, (uint32_t)TSZ);
        const int p0 = g_tile_pos[tile * 4];
#pragma unroll
        for (int q = 0; q < 4; q++) {
            int sp = g_tile_pos[tile * 4 + q];
            if (sp < 0) sp = p0;
            tma2d(s0 + q * 4096, &tmaA, (ag & 15) * 64, sp * B_, mbar);
        }
    };

    float acc[4][4][4];
#pragma unroll
    for (int i = 0; i < 4; i++)
#pragma unroll
        for (int j = 0; j < 4; j++)
#pragma unroll
            for (int q = 0; q < 4; q++) acc[i][j][q] = 0.0f;

    if (tid == 0) { produceA(0); produceA(1); produceB(0); produceB(1); }

    for (int sg = 0; sg < totB; sg++) {
        if (tid == 0) {
            const int psB = sg + 2;
            if (psB < totB) {
                const int pw = psB / NST;
                if (pw >= 1) MBAR_WAIT(sbase + (psB % NST) * 16 + 8, (pw - 1) & 1);
                produceB(psB);
            }
            if (!(sg & 1)) {
                const int psA = (sg >> 1) + 2;
                if (psA < totA) {
                    const int pw = psA / NST;
                    if (pw >= 1) MBAR_WAIT(sbase + 64 + (psA % NST) * 16 + 8, (pw - 1) & 1);
                    produceA(psA);
                }
            }
        }
        const int stB = sg % NST;
        const int ag = sg >> 1;
        const int stA = ag % NST;
        MBAR_WAIT(sbase + stB * 16, (sg / NST) & 1);
        if (!(sg & 1)) MBAR_WAIT(sbase + 64 + stA * 16, (ag / NST) & 1);

        const uint32_t aT = sbase + SM_TILES + A_OFF + stA * TSZ + aRowOff;
        const uint32_t bT = sbase + SM_TILES + B_OFF + stB * TSZ + bRow;
#pragma unroll
        for (int kk = 0; kk < 2; kk++) {
            const int k4 = ((sg & 1) << 1) | kk;
            uint32_t ah[4][4];
#pragma unroll
            for (int mi = 0; mi < 4; mi++)
                ldsm4(ah[mi], aT + mi * 2048 + aCh[k4]);
#pragma unroll
            for (int ni = 0; ni < 4; ni++) {
                float f0, f1, f2, f3;
                lds2f(f0, f1, bT + ni * 1024 + bO0[kk]);
                lds2f(f2, f3, bT + ni * 1024 + bO1[kk]);
                uint32_t bb[2];
                bb[0] = pkf16(f0, f1);
                bb[1] = pkf16(f2, f3);
#pragma unroll
                for (int mi = 0; mi < 4; mi++)
                    mma16816(acc[mi][ni], ah[mi], bb);
            }
        }
        MBAR_ARRIVE(sbase + stB * 16 + 8);
        if (sg & 1) MBAR_ARRIVE(sbase + 64 + stA * 16 + 8);

        // ---- item boundary: epilogue + acc reset ----
        if ((sg & 31) == 31) {
            const int item = blockIdx.x + (sg >> 5) * NPERS;
            const int tile = item >> 3;
            const int otile = (item & 7) * 128;
            const int gcol = otile + n32 + 2 * (lane & 3);
#pragma unroll
            for (int mi = 0; mi < 4; mi++) {
                const int row0 = m64 + mi * 16 + (lane >> 2);
                const int slot = row0 >> 5;
                const int spos = g_tile_pos[tile * 4 + slot];
                if (spos >= 0) {
                    float* base0 = out + ((size_t)(row0 & 31) * S_ + spos) * O_ + gcol;
                    float* base1 = out + ((size_t)((row0 + 8) & 31) * S_ + spos) * O_ + gcol;
#pragma unroll
                    for (int ni = 0; ni < 4; ni++) {
                        *(float2*)(base0 + ni * 8) =
                            make_float2(acc[mi][ni][0], acc[mi][ni][1]);
                        *(float2*)(base1 + ni * 8) =
                            make_float2(acc[mi][ni][2], acc[mi][ni][3]);
                    }
                }
#pragma unroll
                for (int ni = 0; ni < 4; ni++)
#pragma unroll
                    for (int q = 0; q < 4; q++) acc[mi][ni][q] = 0.0f;
            }
        }
    }
}

// ---------------- host ----------------
typedef CUresult (*tma_encode_fn)(
    CUtensorMap*, CUtensorMapDataType, cuuint32_t, void*,
    const cuuint64_t*, const cuuint64_t*, const cuuint32_t*, const cuuint32_t*,
    CUtensorMapInterleave, CUtensorMapSwizzle, CUtensorMapL2promotion,
    CUtensorMapFloatOOBfill);

extern "C" void kernel_launch(void* const* d_in, const int* in_sizes, int n_in,
                              void* d_out, int out_size) {
    const float* x = (const float*)d_in[0];
    const int* idx = (const int*)d_in[1];
    const float* w = (const float*)d_in[2];
    float* out = (float*)d_out;

    static CUtensorMap h_tma_a, h_tma_b;
    static bool init_done = false;
    if (!init_done) {
        cudaFuncSetAttribute(moshi_gemm_kernel,
                             cudaFuncAttributeMaxDynamicSharedMemorySize, SMEM_TOTAL);
        void* pa = nullptr;
        cudaGetSymbolAddress(&pa, g_x16);
        tma_encode_fn enc = nullptr;
        cudaDriverEntryPointQueryResult qr;
        cudaGetDriverEntryPointByVersion("cuTensorMapEncodeTiled", (void**)&enc,
                                         12000, cudaEnableDefault, &qr);
        cuuint64_t dimsA[2] = {(cuuint64_t)D_, (cuuint64_t)(S_ * B_)};
        cuuint64_t strA[1]  = {(cuuint64_t)D_ * 2};
        cuuint32_t boxA[2]  = {64, 32};
        cuuint32_t es[2]    = {1, 1};
        enc(&h_tma_a, CU_TENSOR_MAP_DATA_TYPE_FLOAT16, 2, pa, dimsA, strA, boxA, es,
            CU_TENSOR_MAP_INTERLEAVE_NONE, CU_TENSOR_MAP_SWIZZLE_128B,
            CU_TENSOR_MAP_L2_PROMOTION_L2_128B, CU_TENSOR_MAP_FLOAT_OOB_FILL_NONE);
        cuuint64_t dimsB[2] = {(cuuint64_t)D_, (cuuint64_t)(L_ * O_)};
        cuuint64_t strB[1]  = {(cuuint64_t)D_ * 4};
        cuuint32_t boxB[2]  = {32, 128};
        enc(&h_tma_b, CU_TENSOR_MAP_DATA_TYPE_FLOAT32, 2, (void*)w, dimsB, strB, boxB, es,
            CU_TENSOR_MAP_INTERLEAVE_NONE, CU_TENSOR_MAP_SWIZZLE_128B,
            CU_TENSOR_MAP_L2_PROMOTION_L2_128B, CU_TENSOR_MAP_FLOAT_OOB_FILL_NONE);
        init_done = true;
    }

    conv_kernel<<<XBLKS + 1, 256>>>(x, idx);
    moshi_gemm_kernel<<<NPERS, THREADS, SMEM_TOTAL>>>(h_tma_a, h_tma_b, out);
}